// round 4
// baseline (speedup 1.0000x reference)
#include <cuda_runtime.h>
#include <cuda_bf16.h>

#define N_PRED   1024
#define M_GT     2048
#define P        20
#define THREADS  256
#define M_PER_T  (M_GT / THREADS)   // 8

typedef unsigned long long u64;

__device__ __forceinline__ float fsqrt_approx(float x) {
    float r;
    asm("sqrt.approx.f32 %0, %1;" : "=f"(r) : "f"(x));
    return r;
}

__device__ __forceinline__ u64 pack2(float lo, float hi) {
    u64 r;
    asm("mov.b64 %0, {%1, %2};"
        : "=l"(r) : "r"(__float_as_uint(lo)), "r"(__float_as_uint(hi)));
    return r;
}
__device__ __forceinline__ void unpack2(u64 v, float& lo, float& hi) {
    unsigned a, b;
    asm("mov.b64 {%0, %1}, %2;" : "=r"(a), "=r"(b) : "l"(v));
    lo = __uint_as_float(a);
    hi = __uint_as_float(b);
}
__device__ __forceinline__ u64 add2(u64 a, u64 b) {
    u64 r;
    asm("add.rn.f32x2 %0, %1, %2;" : "=l"(r) : "l"(a), "l"(b));
    return r;
}
__device__ __forceinline__ u64 mul2(u64 a, u64 b) {
    u64 r;
    asm("mul.rn.f32x2 %0, %1, %2;" : "=l"(r) : "l"(a), "l"(b));
    return r;
}
__device__ __forceinline__ u64 fma2(u64 a, u64 b, u64 c) {
    u64 r;
    asm("fma.rn.f32x2 %0, %1, %2, %3;" : "=l"(r) : "l"(a), "l"(b), "l"(c));
    return r;
}

// Fast inverse-sqrt seed (per 32-bit lane, ALU pipe only).
__device__ __forceinline__ float rsqrt_seed(float x) {
    unsigned i = __float_as_uint(x);
    i = 0x5f3759dfu - (i >> 1);
    return __uint_as_float(i);
}

__global__ __launch_bounds__(THREADS)
void PointMatcher_29437705847326_kernel(const float* __restrict__ pred,
                                        const float* __restrict__ gt,
                                        float* __restrict__ out_points,
                                        float* __restrict__ out_conf,
                                        float* __restrict__ out_idx) {
    const int n   = blockIdx.x;
    const int tid = threadIdx.x;

    // Pre-pack this block's pred row, NEGATED, as packed x-lanes / y-lanes,
    // so d = g + (-p) via add.f32x2 (squaring is sign-invariant).
    const float4* pr = reinterpret_cast<const float4*>(pred + n * (P * 2));
    u64 npx[10], npy[10];
#pragma unroll
    for (int i = 0; i < 10; i++) {
        float4 p = pr[i];
        npx[i] = pack2(-p.x, -p.z);
        npy[i] = pack2(-p.y, -p.w);
    }

    const u64 c_neg_half = pack2(-0.5f, -0.5f);
    const u64 c_1p5      = pack2(1.5f, 1.5f);

    float best  = 3.4e38f;
    int   bestm = 0;

#pragma unroll
    for (int j = 0; j < M_PER_T; j++) {
        const int m = j * THREADS + tid;           // coalesced across threads
        const float4* gr = reinterpret_cast<const float4*>(gt + m * (P * 2));
        u64 acc2 = 0;                              // packed (0.0f, 0.0f)
#pragma unroll
        for (int i = 0; i < 10; i++) {
            float4 g = gr[i];
            u64 gx = pack2(g.x, g.z);
            u64 gy = pack2(g.y, g.w);
            u64 dx = add2(gx, npx[i]);             // g - p (x lanes, 2 points)
            u64 dy = add2(gy, npy[i]);             // g - p (y lanes)
            u64 s  = fma2(dy, dy, mul2(dx, dx));   // dx^2 + dy^2, packed

            if (i == 0) {
                // FMA-pipe sqrt path (offloads 10% of sqrts from MUFU):
                // rsqrt magic seed + 3 packed Newton iterations (rel err
                // converges to the f32 rounding floor ~1e-7, matching MUFU,
                // to keep argmin tie-breaks identical to the reference).
                float s0, s1;
                unpack2(s, s0, s1);
                s0 = fmaxf(s0, 1e-35f);            // guard 0*inf -> NaN
                s1 = fmaxf(s1, 1e-35f);
                u64 sc  = pack2(s0, s1);
                u64 r   = pack2(rsqrt_seed(s0), rsqrt_seed(s1));
                u64 nxh = mul2(sc, c_neg_half);    // -0.5*s (reused 3x)
                r = mul2(r, fma2(nxh, mul2(r, r), c_1p5));   // iter 1
                r = mul2(r, fma2(nxh, mul2(r, r), c_1p5));   // iter 2
                r = mul2(r, fma2(nxh, mul2(r, r), c_1p5));   // iter 3
                acc2 = add2(acc2, mul2(sc, r));    // sqrt(s) = s * rsqrt(s)
            } else {
                // MUFU path
                float s0, s1;
                unpack2(s, s0, s1);
                acc2 = add2(acc2, pack2(fsqrt_approx(s0), fsqrt_approx(s1)));
            }
        }
        float a0, a1;
        unpack2(acc2, a0, a1);
        float acc = a0 + a1;
        // m ascends within a thread; strict < keeps the first (smallest) index.
        if (acc < best) { best = acc; bestm = m; }
    }

    // Block min+argmin reduction with smaller-index tie-break.
    __shared__ float smin[THREADS];
    __shared__ int   sidx[THREADS];
    smin[tid] = best;
    sidx[tid] = bestm;
    __syncthreads();
#pragma unroll
    for (int s = THREADS / 2; s > 0; s >>= 1) {
        if (tid < s) {
            float o  = smin[tid + s];
            int   oi = sidx[tid + s];
            float c  = smin[tid];
            int   ci = sidx[tid];
            if (o < c || (o == c && oi < ci)) {
                smin[tid] = o;
                sidx[tid] = oi;
            }
        }
        __syncthreads();
    }

    const int   bm = sidx[0];
    const float md = smin[0] * (1.0f / (float)P);   // mean distance

    // Gather matched gt row -> out_points[n]
    const float4* gbest = reinterpret_cast<const float4*>(gt + bm * (P * 2));
    float4* op = reinterpret_cast<float4*>(out_points + n * (P * 2));
    if (tid < 10) op[tid] = gbest[tid];

    if (tid == 0) {
        float conf = (md > 2.0f) ? 0.0f : __expf(-md);
        out_conf[n] = conf;
        out_idx[n]  = (float)bm;
    }
}

extern "C" void kernel_launch(void* const* d_in, const int* in_sizes, int n_in,
                              void* d_out, int out_size) {
    const float* pred = (const float*)d_in[0];   // (1024, 20, 2) f32
    const float* gt   = (const float*)d_in[1];   // (2048, 20, 2) f32
    float* out = (float*)d_out;

    // Output layout (reference return order, flattened):
    //   matched_points : N_PRED * P * 2 = 40960 floats
    //   confidence     : N_PRED         =  1024 floats
    //   matched_indices: N_PRED         =  1024 (written as float values)
    float* out_points = out;
    float* out_conf   = out + N_PRED * P * 2;
    float* out_idx    = out + N_PRED * P * 2 + N_PRED;

    PointMatcher_29437705847326_kernel<<<N_PRED, THREADS>>>(
        pred, gt, out_points, out_conf, out_idx);
}